// round 2
// baseline (speedup 1.0000x reference)
#include <cuda_runtime.h>
#include <stdint.h>

// CritiGraph: ct_val[t,s,c,p] = (sum_p' d(sta,pos) - d(sta,pos)[p] + d(cnc,pos)[c,p]) / TP
// d(a,b,norm) = sign(a)*sign(b) * (1 - e/16) * norm, e = frexp_exp(|a|^|b| + 1)
//
// Shapes: T=128, S=128, C=257, TP=8, H=16. Output (T,S,C,TP) fp32 = 134.7MB -> store bound.

#define Tn 128
#define Sn 128
#define Cn 257
#define TPn 8
#define S_CHUNK 16

__global__ __launch_bounds__(256, 1)
void critigraph_kernel(const int* __restrict__ sta_loc,   // (T, TP)
                       const int* __restrict__ pos_loc,   // (T, S, TP)
                       const int* __restrict__ cnc_loc,   // (T, C, TP)
                       const float* __restrict__ eu_norm, // (T, S)
                       float* __restrict__ out)           // (T, S, C, TP)
{
    __shared__ __align__(16) uint32_t sm_acw[Cn * TPn];     // |cnc| | (neg<<31)
    __shared__ __align__(16) uint32_t sm_apw[S_CHUNK][TPn]; // |pos| | (neg<<31)
    __shared__ __align__(16) float    sm_fb[S_CHUNK][TPn];  // (sum - csp)/8
    __shared__ uint32_t sm_nsb[S_CHUNK];                    // bits(norm/8)
    __shared__ float    sm_lut[17];                         // (clz-1)/16

    const int t   = blockIdx.x;       // 0..127
    const int s0  = blockIdx.y * S_CHUNK;
    const int tid = threadIdx.x;

    // ---- stage cnc row t into smem, sign-packed ----
    const int* cnc_t = cnc_loc + (size_t)t * (Cn * TPn);
    #pragma unroll 3
    for (int i = tid; i < Cn * TPn; i += 256) {
        int v = cnc_t[i];
        uint32_t a = (uint32_t)(v < 0 ? -v : v);
        sm_acw[i] = a | ((uint32_t)(v < 0) << 31);
    }
    if (tid < 17) sm_lut[tid] = (float)(tid - 1) * 0.0625f;

    // ---- phase A: per-(s,p) constants (threads 0..127, 4 full warps) ----
    if (tid < S_CHUNK * TPn) {
        const int sl = tid >> 3, p = tid & 7;
        const int s  = s0 + sl;
        const int pv = pos_loc[((size_t)t * Sn + s) * TPn + p];
        const uint32_t ap = (uint32_t)(pv < 0 ? -pv : pv);
        const int sv = sta_loc[t * TPn + p];
        const uint32_t as_ = (uint32_t)(sv < 0 ? -sv : sv);
        const float norm = eu_norm[t * Sn + s];

        // d(sta, pos): e = frexp exponent of (xor+1); w = 1 - e/16 = (clz((xor+1)<<15)-1)/16
        const uint32_t x = as_ ^ ap;
        const int cl = __clz(x * 32768u + 32768u);
        float d = (float)(cl - 1) * 0.0625f * norm;
        if ((pv < 0) != (sv < 0)) d = -d;

        // octet reduction over p (lanes 8k..8k+7)
        float sum = d;
        sum += __shfl_xor_sync(0xffffffffu, sum, 1);
        sum += __shfl_xor_sync(0xffffffffu, sum, 2);
        sum += __shfl_xor_sync(0xffffffffu, sum, 4);

        sm_fb[sl][p]  = (sum - d) * 0.125f;
        sm_apw[sl][p] = ap | ((uint32_t)(pv < 0) << 31);
        if (p == 0) sm_nsb[sl] = __float_as_uint(norm * 0.125f);
    }
    __syncthreads();

    // ---- phase B: each thread owns one p-half (p0..p0+3), sweeps c ----
    const int p0 = (tid & 1) * 4;
    float* out_base = out + ((size_t)t * Sn + s0) * (size_t)(Cn * TPn);

    for (int sl = 0; sl < S_CHUNK; sl++) {
        const uint4  apw4 = *(const uint4*)&sm_apw[sl][p0];
        const float4 fb4  = *(const float4*)&sm_fb[sl][p0];
        const uint32_t nsb = sm_nsb[sl];
        float* out_s = out_base + (size_t)sl * (Cn * TPn);

        for (int v = tid; v < 2 * Cn; v += 256) {
            // v encodes (c = v>>1, half = v&1 == tid&1); smem & gmem offsets are v*16B
            const uint4 acw4 = *(const uint4*)&sm_acw[v * 4];
            float4 r;
            {
                const uint32_t tt = acw4.x ^ apw4.x;
                const int cl = __clz(tt * 32768u + 32768u);
                const uint32_t m = nsb ^ (tt & 0x80000000u);
                r.x = fmaf(sm_lut[cl], __uint_as_float(m), fb4.x);
            }
            {
                const uint32_t tt = acw4.y ^ apw4.y;
                const int cl = __clz(tt * 32768u + 32768u);
                const uint32_t m = nsb ^ (tt & 0x80000000u);
                r.y = fmaf(sm_lut[cl], __uint_as_float(m), fb4.y);
            }
            {
                const uint32_t tt = acw4.z ^ apw4.z;
                const int cl = __clz(tt * 32768u + 32768u);
                const uint32_t m = nsb ^ (tt & 0x80000000u);
                r.z = fmaf(sm_lut[cl], __uint_as_float(m), fb4.z);
            }
            {
                const uint32_t tt = acw4.w ^ apw4.w;
                const int cl = __clz(tt * 32768u + 32768u);
                const uint32_t m = nsb ^ (tt & 0x80000000u);
                r.w = fmaf(sm_lut[cl], __uint_as_float(m), fb4.w);
            }
            *(float4*)&out_s[(size_t)v * 4] = r;
        }
    }
}

extern "C" void kernel_launch(void* const* d_in, const int* in_sizes, int n_in,
                              void* d_out, int out_size)
{
    const int*   sta = (const int*)d_in[0];
    const int*   pos = (const int*)d_in[1];
    const int*   cnc = (const int*)d_in[2];
    const float* eu  = (const float*)d_in[3];
    dim3 grid(Tn, Sn / S_CHUNK);  // (128, 8)
    critigraph_kernel<<<grid, 256>>>(sta, pos, cnc, eu, (float*)d_out);
}

// round 3
// speedup vs baseline: 1.1346x; 1.1346x over previous
#include <cuda_runtime.h>
#include <stdint.h>

// CritiGraph: ct_val[t,s,c,p] = (sum_p' d - d[p] + d(cnc,pos)[c,p]) / TP
// d(a,b,norm) = sign(a)*sign(b) * (1 - e/16) * norm, e = frexp_exp(|a|^|b| + 1)
// Shapes: T=128, S=128, C=257, TP=8. Output 134.7MB fp32 -> HBM-write bound (~20us floor).

#define Tn 128
#define Sn 128
#define Cn 257
#define TPn 8
#define S_CHUNK 16
#define ROW_FLOATS (Cn * TPn)   // 2056 floats per (t,s) row
#define ROW_VEC4   (2 * Cn)     // 514 float4 per row

__device__ __forceinline__ uint32_t packsgn(int v) {
    // |v| (<= 65535, fits low 16 bits) with sign in bit 31
    uint32_t a = (uint32_t)(v < 0 ? -v : v);
    return a | ((uint32_t)v & 0x80000000u);
}

__device__ __forceinline__ float elem(uint32_t aw, uint32_t pw, uint32_t nsb,
                                      float fb, const float* __restrict__ lut) {
    // xor of packed words: bit31 = sign product, low16 = |a|^|b|
    const uint32_t tt = aw ^ pw;
    // ( (xor&0xFFFF) + 1 ) << 15 ; bit31 of tt shifts out automatically
    const int cl = __clz(tt * 32768u + 32768u);          // frexp exp -> (cl-1)/16 weight
    const uint32_t m = nsb ^ (tt & 0x80000000u);         // sign-folded norm/8
    return fmaf(lut[cl], __uint_as_float(m), fb);
}

__global__ __launch_bounds__(256, 7)
void critigraph_kernel(const int* __restrict__ sta_loc,   // (T, TP)
                       const int* __restrict__ pos_loc,   // (T, S, TP)
                       const int* __restrict__ cnc_loc,   // (T, C, TP)
                       const float* __restrict__ eu_norm, // (T, S)
                       float* __restrict__ out)           // (T, S, C, TP)
{
    __shared__ __align__(16) uint32_t sm_apw[S_CHUNK][TPn]; // |pos| | (neg<<31)
    __shared__ __align__(16) float    sm_fb[S_CHUNK][TPn];  // (sum - d[p]) / 8
    __shared__ uint32_t sm_nsb[S_CHUNK];                    // bits(norm/8)
    __shared__ float    sm_lut[17];                         // (clz-1)/16

    const int t   = blockIdx.x;
    const int s0  = blockIdx.y * S_CHUNK;
    const int tid = threadIdx.x;

    if (tid < 17) sm_lut[tid] = (float)(tid - 1) * 0.0625f;

    // ---- phase A: per-(s,p) constants (threads 0..127) ----
    if (tid < S_CHUNK * TPn) {
        const int sl = tid >> 3, p = tid & 7;
        const int s  = s0 + sl;
        const int pv = pos_loc[((size_t)t * Sn + s) * TPn + p];
        const uint32_t ap = (uint32_t)(pv < 0 ? -pv : pv);
        const int sv = sta_loc[t * TPn + p];
        const uint32_t as_ = (uint32_t)(sv < 0 ? -sv : sv);
        const float norm = eu_norm[t * Sn + s];

        const uint32_t x = as_ ^ ap;
        const int cl = __clz(x * 32768u + 32768u);
        float d = (float)(cl - 1) * 0.0625f * norm;
        if ((pv < 0) != (sv < 0)) d = -d;

        // octet reduction over p (lanes 8k..8k+7)
        float sum = d;
        sum += __shfl_xor_sync(0xffffffffu, sum, 1);
        sum += __shfl_xor_sync(0xffffffffu, sum, 2);
        sum += __shfl_xor_sync(0xffffffffu, sum, 4);

        sm_fb[sl][p]  = (sum - d) * 0.125f;
        sm_apw[sl][p] = ap | ((uint32_t)pv & 0x80000000u);
        if (p == 0) sm_nsb[sl] = __float_as_uint(norm * 0.125f);
    }

    // ---- register-resident cnc: thread owns vec4 columns v=tid, tid+256 (+512 for tid<2) ----
    const uint4* cnc_t = (const uint4*)(cnc_loc + (size_t)t * ROW_FLOATS);
    uint4 a0 = cnc_t[tid];
    uint4 a1 = cnc_t[tid + 256];
    uint4 a2 = make_uint4(0u, 0u, 0u, 0u);
    if (tid < 2) a2 = cnc_t[tid + 512];

    a0.x = packsgn((int)a0.x); a0.y = packsgn((int)a0.y);
    a0.z = packsgn((int)a0.z); a0.w = packsgn((int)a0.w);
    a1.x = packsgn((int)a1.x); a1.y = packsgn((int)a1.y);
    a1.z = packsgn((int)a1.z); a1.w = packsgn((int)a1.w);
    a2.x = packsgn((int)a2.x); a2.y = packsgn((int)a2.y);
    a2.z = packsgn((int)a2.z); a2.w = packsgn((int)a2.w);

    __syncthreads();

    // v=tid and v=tid+256 (and tid+512) share parity -> same p-half for all stores
    const int p0 = (tid & 1) * 4;
    float* ptr = out + ((size_t)t * Sn + s0) * ROW_FLOATS + (size_t)tid * 4;

    #pragma unroll
    for (int sl = 0; sl < S_CHUNK; sl++) {
        const uint4  apw = *(const uint4*)&sm_apw[sl][p0];
        const float4 fb  = *(const float4*)&sm_fb[sl][p0];
        const uint32_t nsb = sm_nsb[sl];

        float4 r0, r1;
        r0.x = elem(a0.x, apw.x, nsb, fb.x, sm_lut);
        r0.y = elem(a0.y, apw.y, nsb, fb.y, sm_lut);
        r0.z = elem(a0.z, apw.z, nsb, fb.z, sm_lut);
        r0.w = elem(a0.w, apw.w, nsb, fb.w, sm_lut);
        r1.x = elem(a1.x, apw.x, nsb, fb.x, sm_lut);
        r1.y = elem(a1.y, apw.y, nsb, fb.y, sm_lut);
        r1.z = elem(a1.z, apw.z, nsb, fb.z, sm_lut);
        r1.w = elem(a1.w, apw.w, nsb, fb.w, sm_lut);

        __stcs((float4*)ptr, r0);
        __stcs((float4*)(ptr + 1024), r1);   // +256 float4

        if (tid < 2) {
            float4 r2;
            r2.x = elem(a2.x, apw.x, nsb, fb.x, sm_lut);
            r2.y = elem(a2.y, apw.y, nsb, fb.y, sm_lut);
            r2.z = elem(a2.z, apw.z, nsb, fb.z, sm_lut);
            r2.w = elem(a2.w, apw.w, nsb, fb.w, sm_lut);
            __stcs((float4*)(ptr + 2048), r2); // +512 float4
        }

        ptr += ROW_FLOATS;
    }
}

extern "C" void kernel_launch(void* const* d_in, const int* in_sizes, int n_in,
                              void* d_out, int out_size)
{
    const int*   sta = (const int*)d_in[0];
    const int*   pos = (const int*)d_in[1];
    const int*   cnc = (const int*)d_in[2];
    const float* eu  = (const float*)d_in[3];
    dim3 grid(Tn, Sn / S_CHUNK);  // (128, 8) -> 1024 blocks, all co-resident
    critigraph_kernel<<<grid, 256>>>(sta, pos, cnc, eu, (float*)d_out);
}